// round 15
// baseline (speedup 1.0000x reference)
#include <cuda_runtime.h>
#include <cuda_bf16.h>
#include <math.h>
#include <stdint.h>

// ---------------- problem constants ----------------
#define BSZ 32768
#define DM  1024
#define NHD 8
#define HD  128
#define HIDM 1024
#define KSZ 4
#define EPSV 1e-6f
#define CAPV 15.0f

// split scale: s = 1/16
#define SPLIT_S    0.0625f
#define SPLIT_INV  16.0f
#define SPLIT_1MS  0.9375f

// ---------------- GEMM tiling ----------------
#define NCHUNK 32            // K_eff = 2048 = 32 chunks of 64 bf16 (16 main + 16 cor)
#define NS 4                 // pipeline stages
#define TM 128
#define TN 256
#define CHUNK_A 16384        // 128 rows x 128B (64 bf16)
#define CHUNK_B 32768        // 256 rows x 128B
#define STG (CHUNK_A + CHUNK_B)
#define SMEM_OFF 1024
#define SMEM_TOTAL (SMEM_OFF + NS * STG)

#define NMTILE (BSZ / TM)    // 256

// ---------------- device scratch (no allocs) ----------------
__device__ __nv_bfloat16 g_Ahi[(size_t)BSZ * DM];
__device__ __nv_bfloat16 g_Acor[(size_t)BSZ * DM];
__device__ __nv_bfloat16 g_Hhi[(size_t)BSZ * HIDM];
__device__ __nv_bfloat16 g_Hcor[(size_t)BSZ * HIDM];
__device__ __nv_bfloat16 g_W1[(size_t)2048 * 2048];   // [ntile8(256)][32][256x64 swz]
__device__ __nv_bfloat16 g_W2[(size_t)1024 * 2048];   // [ntile4(256)][32][256x64 swz]
__device__ float g_xconv[(size_t)BSZ * DM];
__device__ float g_z[(size_t)BSZ * HIDM];
__device__ int   g_cnt[NMTILE];

// ---------------- PTX helpers (all non-'a' features) ----------------
__device__ __forceinline__ uint32_t swz128(uint32_t off) { return off ^ ((off >> 3) & 0x70); }

__device__ __forceinline__ uint32_t s2u(const void* p) {
    uint32_t a;
    asm("{ .reg .u64 t; cvta.to.shared.u64 t, %1; cvt.u32.u64 %0, t; }" : "=r"(a) : "l"(p));
    return a;
}
__device__ __forceinline__ void mbar_init(uint32_t mbar, uint32_t cnt) {
    asm volatile("mbarrier.init.shared.b64 [%0], %1;" :: "r"(mbar), "r"(cnt) : "memory");
}
__device__ __forceinline__ void mbar_expect(uint32_t mbar, uint32_t bytes) {
    asm volatile("mbarrier.arrive.expect_tx.shared.b64 _, [%0], %1;" :: "r"(mbar), "r"(bytes) : "memory");
}
__device__ __forceinline__ void mbar_arrive(uint32_t mbar) {
    asm volatile("mbarrier.arrive.shared.b64 _, [%0];" :: "r"(mbar) : "memory");
}
__device__ __forceinline__ void mbar_wait(uint32_t mbar, uint32_t parity) {
    uint32_t done;
    asm volatile("{\n\t.reg .pred p;\n\t"
        "mbarrier.try_wait.parity.acquire.cta.shared::cta.b64 p, [%1], %2;\n\t"
        "selp.b32 %0, 1, 0, p;\n\t}"
        : "=r"(done) : "r"(mbar), "r"(parity) : "memory");
    while (!done) {
        asm volatile("{\n\t.reg .pred p;\n\t"
            "mbarrier.try_wait.parity.acquire.cta.shared::cta.b64 p, [%1], %2, 0x989680;\n\t"
            "selp.b32 %0, 1, 0, p;\n\t}"
            : "=r"(done) : "r"(mbar), "r"(parity) : "memory");
    }
}
__device__ __forceinline__ void bulk_g2s(uint32_t dst, const void* src, uint32_t bytes, uint32_t mbar) {
    asm volatile("cp.async.bulk.shared::cluster.global.mbarrier::complete_tx::bytes [%0], [%1], %2, [%3];"
        :: "r"(dst), "l"(src), "r"(bytes), "r"(mbar) : "memory");
}
__device__ __forceinline__ void ldmx4(uint32_t* r, uint32_t addr) {
    asm volatile("ldmatrix.sync.aligned.m8n8.x4.shared.b16 {%0,%1,%2,%3}, [%4];"
        : "=r"(r[0]), "=r"(r[1]), "=r"(r[2]), "=r"(r[3]) : "r"(addr));
}
__device__ __forceinline__ void mma16816(float* d, const uint32_t* a, uint32_t b0, uint32_t b1) {
    asm volatile("mma.sync.aligned.m16n8k16.row.col.f32.bf16.bf16.f32 "
        "{%0,%1,%2,%3}, {%4,%5,%6,%7}, {%8,%9}, {%0,%1,%2,%3};"
        : "+f"(d[0]), "+f"(d[1]), "+f"(d[2]), "+f"(d[3])
        : "r"(a[0]), "r"(a[1]), "r"(a[2]), "r"(a[3]), "r"(b0), "r"(b1));
}
__device__ __forceinline__ void barc(int) {
    asm volatile("bar.sync 1, 256;" ::: "memory");
}

__device__ __forceinline__ float softcap_f(float x) {
    return CAPV * tanhf(x * (1.0f / CAPV));
}

// ---------------- prep: weight pack + input convert + counter reset --------
// blocks [0, 6144): weight packing (W1=[conv_tap|z_w], W2=out_w),
//   segments per N-tile of 256 rows: [0:16)=W_hi, [16:32)=W_cor=bf16(W_hi+W_lo/s).
// blocks [6144, 6144+32768): inputs -> blocked swizzled bf16 hi/cor.
__global__ __launch_bounds__(256) void prep_kernel(const float* __restrict__ conv_w,
                                                   const float* __restrict__ z_w,
                                                   const float* __restrict__ out_w,
                                                   const float* __restrict__ inp) {
    if (blockIdx.x == 0 && threadIdx.x < NMTILE) g_cnt[threadIdx.x] = 0;

    if (blockIdx.x < 6144) {
        int idx = blockIdx.x * 256 + threadIdx.x;   // < 3072*512
        int n = idx >> 9;
        int k = (idx & 511) << 1;
        float v0, v1;
        if (n < 1024) {
            v0 = conv_w[((size_t)n * DM + k) * KSZ + (KSZ - 1)];
            v1 = conv_w[((size_t)n * DM + k + 1) * KSZ + (KSZ - 1)];
        } else if (n < 2048) {
            const float* p = &z_w[(size_t)(n - 1024) * DM + k];
            v0 = p[0]; v1 = p[1];
        } else {
            const float* p = &out_w[(size_t)(n - 2048) * DM + k];
            v0 = p[0]; v1 = p[1];
        }
        __nv_bfloat16 h0 = __float2bfloat16(v0), h1 = __float2bfloat16(v1);
        float h0f = __bfloat162float(h0), h1f = __bfloat162float(h1);
        __nv_bfloat162 hp; hp.x = h0; hp.y = h1;
        __nv_bfloat162 cp;
        cp.x = __float2bfloat16(h0f + (v0 - h0f) * SPLIT_INV);
        cp.y = __float2bfloat16(h1f + (v1 - h1f) * SPLIT_INV);

        char* base; int nl;
        if (n < 2048) { base = (char*)g_W1; nl = n; }
        else          { base = (char*)g_W2; nl = n - 2048; }
        int ntile = nl >> 8, nr = nl & 255;
        int kc = k >> 6;
        uint32_t inoff = swz128((uint32_t)nr * 128 + (uint32_t)(k & 63) * 2);
        size_t b0 = ((size_t)(ntile * NCHUNK + kc)) * CHUNK_B + inoff;
        size_t b1 = ((size_t)(ntile * NCHUNK + 16 + kc)) * CHUNK_B + inoff;
        *(__nv_bfloat162*)(base + b0) = hp;
        *(__nv_bfloat162*)(base + b1) = cp;
    } else {
        int idx = (blockIdx.x - 6144) * 256 + threadIdx.x;   // BSZ*256
        int b = idx >> 8;
        int k = (idx & 255) << 2;
        float4 v = *(const float4*)&inp[(size_t)b * DM + k];
        __nv_bfloat16 h0 = __float2bfloat16(v.x), h1 = __float2bfloat16(v.y);
        __nv_bfloat16 h2 = __float2bfloat16(v.z), h3 = __float2bfloat16(v.w);
        float f0 = __bfloat162float(h0), f1 = __bfloat162float(h1);
        float f2 = __bfloat162float(h2), f3 = __bfloat162float(h3);
        __nv_bfloat162 hp0; hp0.x = h0; hp0.y = h1;
        __nv_bfloat162 hp1; hp1.x = h2; hp1.y = h3;
        __nv_bfloat162 cp0, cp1;
        cp0.x = __float2bfloat16((v.x - f0) + f0 * SPLIT_S);
        cp0.y = __float2bfloat16((v.y - f1) + f1 * SPLIT_S);
        cp1.x = __float2bfloat16((v.z - f2) + f2 * SPLIT_S);
        cp1.y = __float2bfloat16((v.w - f3) + f3 * SPLIT_S);
        uint2 hu, lu;
        hu.x = *(uint32_t*)&hp0; hu.y = *(uint32_t*)&hp1;
        lu.x = *(uint32_t*)&cp0; lu.y = *(uint32_t*)&cp1;
        int mtile = b >> 7, r = b & 127, kc = k >> 6;
        size_t off = ((size_t)(mtile * 16 + kc)) * CHUNK_A +
                     swz128((uint32_t)r * 128 + (uint32_t)(k & 63) * 2);
        *(uint2*)((char*)g_Ahi + off) = hu;
        *(uint2*)((char*)g_Acor + off) = lu;
    }
}

// ---------------- HMMA GEMM, tile 128x256, K_eff=2048 (compensated 2-seg) --
// 9 warps: warp 8 = bulk-copy producer, warps 0-7 = 64x64 compute tiles (2x4).
// acc = P1 (chunks 0-15); acc *= (1-s); acc += P2 (chunks 16-31).
// MODE 0: W=g_W1 (N=2048): ntile<4 -> silu(+bias) -> g_xconv, else -> g_z.
//         Last CTA per mtile additionally runs fused gates+cell+LN for its
//         128 rows (emits c_new/n_new/m_new + Hhi/Hcor for GEMM2).
// MODE 1: W=g_W2 (N=1024): plain store -> out.
template <int MODE>
__global__ __launch_bounds__(288, 1) void hmma_gemm_kernel(
    const float* __restrict__ bias, float* __restrict__ outp,
    const float* __restrict__ inp,
    const float* __restrict__ i_w, const float* __restrict__ i_b,
    const float* __restrict__ f_w, const float* __restrict__ f_b,
    const float* __restrict__ o_w, const float* __restrict__ o_b,
    const float* __restrict__ m_in, float* __restrict__ m_out,
    const float* __restrict__ cst, const float* __restrict__ nst,
    const float* __restrict__ gn_w, const float* __restrict__ gn_b,
    float* __restrict__ c_new, float* __restrict__ n_new) {
    extern __shared__ __align__(1024) char smem[];
    uint32_t sb = s2u(smem);
    const int tid = threadIdx.x, wid = tid >> 5, lane = tid & 31;
    const int mtile = blockIdx.y, ntile = blockIdx.x;

    if (tid == 0) {
        for (int s = 0; s < NS; s++) {
            mbar_init(sb + s * 8, 1);          // full (tx-based)
            mbar_init(sb + 64 + s * 8, 8);     // empty (8 consumer warps)
        }
        asm volatile("fence.proxy.async.shared::cta;" ::: "memory");
    }
    __syncthreads();

    if (wid == 8) {
        if (lane == 0) {
            const __nv_bfloat16* Ahi  = MODE ? g_Hhi  : g_Ahi;
            const __nv_bfloat16* Acor = MODE ? g_Hcor : g_Acor;
            const __nv_bfloat16* W    = MODE ? g_W2   : g_W1;
            for (int c = 0; c < NCHUNK; c++) {
                int s = c & (NS - 1);
                mbar_wait(sb + 64 + s * 8, 1u ^ ((c >> 2) & 1));
                uint32_t full = sb + s * 8;
                mbar_expect(full, STG);
                int seg = c >> 4, kk = c & 15;
                const char* ab = (const char*)(seg ? Acor : Ahi) +
                                 ((size_t)(mtile * 16 + kk)) * CHUNK_A;
                const char* bb = (const char*)W + ((size_t)(ntile * NCHUNK + c)) * CHUNK_B;
                uint32_t da = sb + SMEM_OFF + s * STG;
                bulk_g2s(da, ab, CHUNK_A, full);
                bulk_g2s(da + CHUNK_A, bb, CHUNK_B, full);
            }
        }
        return;
    }

    // consumers: warp (wm, wn) computes 64x64
    const int wm = wid >> 2, wn = wid & 3;
    const int m0 = wm * 64, n0 = wn * 64;
    const int li = lane & 7, lg = lane >> 3;

    float d[32][4];
#pragma unroll
    for (int i = 0; i < 32; i++)
#pragma unroll
        for (int j = 0; j < 4; j++) d[i][j] = 0.0f;

    uint32_t aoff[4], boff[4];
#pragma unroll
    for (int mt = 0; mt < 4; mt++)
        aoff[mt] = (uint32_t)(m0 + mt * 16 + 8 * (lg & 1) + li) * 128;
#pragma unroll
    for (int bt = 0; bt < 4; bt++)
        boff[bt] = (uint32_t)(n0 + bt * 16 + 8 * (lg >> 1) + li) * 128;
    const uint32_t acb = (uint32_t)(lg >> 1) * 16;
    const uint32_t bcb = (uint32_t)(lg & 1) * 16;
    const uint32_t sw  = (uint32_t)li * 16;

    for (int c = 0; c < NCHUNK; c++) {
        int s = c & (NS - 1);
        mbar_wait(sb + s * 8, (c >> 2) & 1);
        uint32_t ab = sb + SMEM_OFF + s * STG;
        uint32_t bb = ab + CHUNK_A;
#pragma unroll
        for (int ks = 0; ks < 4; ks++) {
            uint32_t k2 = (uint32_t)ks * 32;
            uint32_t a[4][4], bf[4][4];
#pragma unroll
            for (int mt = 0; mt < 4; mt++)
                ldmx4(a[mt], ab + aoff[mt] + ((k2 + acb) ^ sw));
#pragma unroll
            for (int bt = 0; bt < 4; bt++)
                ldmx4(bf[bt], bb + boff[bt] + ((k2 + bcb) ^ sw));
#pragma unroll
            for (int mt = 0; mt < 4; mt++)
#pragma unroll
                for (int nt = 0; nt < 8; nt++)
                    mma16816(d[mt * 8 + nt], a[mt],
                             bf[nt >> 1][(nt & 1) * 2], bf[nt >> 1][(nt & 1) * 2 + 1]);
        }
        if (lane == 0) mbar_arrive(sb + 64 + s * 8);
        if (c == 15) {
#pragma unroll
            for (int i = 0; i < 32; i++)
#pragma unroll
                for (int j = 0; j < 4; j++) d[i][j] *= SPLIT_1MS;
        }
    }

    // epilogue
    const int mrow = mtile * TM + m0 + (lane >> 2);
    const int gnb  = ntile * TN + n0 + (lane & 3) * 2;
#pragma unroll
    for (int mt = 0; mt < 4; mt++) {
#pragma unroll
        for (int nt = 0; nt < 8; nt++) {
            const float* dd = d[mt * 8 + nt];
            int gm = mrow + mt * 16;
            int gn = gnb + nt * 8;
            if (MODE == 0) {
                if (ntile < 4) {
                    float a0 = dd[0] + bias[gn], a1 = dd[1] + bias[gn + 1];
                    float a2 = dd[2] + bias[gn], a3 = dd[3] + bias[gn + 1];
                    float2 lo, hi;
                    lo.x = a0 / (1.0f + __expf(-a0)); lo.y = a1 / (1.0f + __expf(-a1));
                    hi.x = a2 / (1.0f + __expf(-a2)); hi.y = a3 / (1.0f + __expf(-a3));
                    *(float2*)&g_xconv[(size_t)gm * DM + gn] = lo;
                    *(float2*)&g_xconv[(size_t)(gm + 8) * DM + gn] = hi;
                } else {
                    float2 lo = {dd[0], dd[1]}, hi = {dd[2], dd[3]};
                    int zc = gn - DM;
                    *(float2*)&g_z[(size_t)gm * HIDM + zc] = lo;
                    *(float2*)&g_z[(size_t)(gm + 8) * HIDM + zc] = hi;
                }
            } else {
                float2 lo = {dd[0], dd[1]}, hi = {dd[2], dd[3]};
                *(float2*)&outp[(size_t)gm * DM + gn] = lo;
                *(float2*)&outp[(size_t)(gm + 8) * DM + gn] = hi;
            }
        }
    }

    if (MODE == 0) {
        // ---- last CTA per mtile runs fused gates + cell update + LN ----
        __shared__ int s_last;
        __threadfence();
        barc(0);
        if (tid == 0) s_last = atomicAdd(&g_cnt[mtile], 1);
        barc(0);
        if (s_last == 7) {
            __threadfence();
            float* s_xc = (float*)(smem + SMEM_OFF);
            float* s_in = s_xc + DM;
            const int h = wid;                  // warp -> head
            for (int r = 0; r < TM; r++) {
                const int b = mtile * TM + r;
                *(float4*)&s_xc[tid * 4] = *(const float4*)&g_xconv[(size_t)b * DM + tid * 4];
                *(float4*)&s_in[tid * 4] = *(const float4*)&inp[(size_t)b * DM + tid * 4];
                barc(0);

                // gate dots (warp h -> head h), float4, butterfly-reduced
                const float* iw = &i_w[h * DM];
                const float* fw = &f_w[h * DM];
                const float* ow = &o_w[h * DM];
                float di = 0.f, df = 0.f, dz = 0.f;
#pragma unroll
                for (int it = 0; it < 8; it++) {
                    int k = it * 128 + lane * 4;
                    float4 x = *(const float4*)&s_xc[k];
                    float4 y = *(const float4*)&s_in[k];
                    float4 wi = *(const float4*)&iw[k];
                    float4 wf = *(const float4*)&fw[k];
                    float4 wo = *(const float4*)&ow[k];
                    di += x.x * wi.x + x.y * wi.y + x.z * wi.z + x.w * wi.w;
                    df += x.x * wf.x + x.y * wf.y + x.z * wf.z + x.w * wf.w;
                    dz += y.x * wo.x + y.y * wo.y + y.z * wo.z + y.w * wo.w;
                }
#pragma unroll
                for (int off = 16; off > 0; off >>= 1) {
                    di += __shfl_xor_sync(0xffffffffu, di, off);
                    df += __shfl_xor_sync(0xffffffffu, df, off);
                    dz += __shfl_xor_sync(0xffffffffu, dz, off);
                }
                float itv = softcap_f(di + i_b[h]);
                float ftv = softcap_f(df + f_b[h]);
                float otv = softcap_f(dz + o_b[h]);
                float flog = -log1pf(expf(-ftv));
                float mv   = m_in[b * NHD + h];
                float mn   = fmaxf(flog + mv, itv);
                float ig = expf(itv - mn);
                float fg = expf(flog + mv - mn);
                float og = 1.0f / (1.0f + expf(-otv));
                if (lane == 0) m_out[b * NHD + h] = mn;

                // cell update + LN (warp h -> head h, 4 elems/lane)
                const int e = lane * 4;
                const int col = h * HD + e;
                const size_t base = (size_t)(b * NHD + h) * HD + e;

                float4 c4 = *(const float4*)&cst[base];
                float4 n4 = *(const float4*)&nst[base];
                float4 z4 = *(const float4*)&g_z[(size_t)b * HIDM + col];

                float cv[4], nv[4], hv[4];
                cv[0] = fg * c4.x + ig * z4.x; cv[1] = fg * c4.y + ig * z4.y;
                cv[2] = fg * c4.z + ig * z4.z; cv[3] = fg * c4.w + ig * z4.w;
                nv[0] = fg * n4.x + ig; nv[1] = fg * n4.y + ig;
                nv[2] = fg * n4.z + ig; nv[3] = fg * n4.w + ig;
#pragma unroll
                for (int j = 0; j < 4; j++) hv[j] = og * cv[j] / (nv[j] + EPSV);

                *(float4*)&c_new[base] = *(float4*)cv;
                *(float4*)&n_new[base] = *(float4*)nv;

                float s = hv[0] + hv[1] + hv[2] + hv[3];
                float s2 = hv[0] * hv[0] + hv[1] * hv[1] + hv[2] * hv[2] + hv[3] * hv[3];
#pragma unroll
                for (int off = 16; off > 0; off >>= 1) {
                    s  += __shfl_xor_sync(0xffffffffu, s, off);
                    s2 += __shfl_xor_sync(0xffffffffu, s2, off);
                }
                float mu  = s * (1.0f / HD);
                float var = s2 * (1.0f / HD) - mu * mu;
                float rs  = rsqrtf(var + EPSV);

                float4 gw = *(const float4*)&gn_w[col];
                float4 gb = *(const float4*)&gn_b[col];
                float hn[4];
                hn[0] = (hv[0] - mu) * rs * gw.x + gb.x;
                hn[1] = (hv[1] - mu) * rs * gw.y + gb.y;
                hn[2] = (hv[2] - mu) * rs * gw.z + gb.z;
                hn[3] = (hv[3] - mu) * rs * gw.w + gb.w;

                __nv_bfloat162 hp0, hp1, cp0, cp1;
                hp0.x = __float2bfloat16(hn[0]); hp0.y = __float2bfloat16(hn[1]);
                hp1.x = __float2bfloat16(hn[2]); hp1.y = __float2bfloat16(hn[3]);
                float f0 = __bfloat162float(hp0.x), f1 = __bfloat162float(hp0.y);
                float f2 = __bfloat162float(hp1.x), f3 = __bfloat162float(hp1.y);
                cp0.x = __float2bfloat16((hn[0] - f0) + f0 * SPLIT_S);
                cp0.y = __float2bfloat16((hn[1] - f1) + f1 * SPLIT_S);
                cp1.x = __float2bfloat16((hn[2] - f2) + f2 * SPLIT_S);
                cp1.y = __float2bfloat16((hn[3] - f3) + f3 * SPLIT_S);
                uint2 hu, lu;
                hu.x = *(uint32_t*)&hp0; hu.y = *(uint32_t*)&hp1;
                lu.x = *(uint32_t*)&cp0; lu.y = *(uint32_t*)&cp1;

                int kc = col >> 6;
                size_t off2 = ((size_t)(mtile * 16 + kc)) * CHUNK_A +
                              swz128((uint32_t)r * 128 + (uint32_t)(col & 63) * 2);
                *(uint2*)((char*)g_Hhi + off2) = hu;
                *(uint2*)((char*)g_Hcor + off2) = lu;

                barc(0);
            }
        }
    }
}

// ---------------- launch ------------------------------------------
extern "C" void kernel_launch(void* const* d_in, const int* in_sizes, int n_in,
                              void* d_out, int out_size) {
    const float* inputs = (const float*)d_in[0];
    const float* c      = (const float*)d_in[1];
    const float* n      = (const float*)d_in[2];
    const float* m      = (const float*)d_in[3];
    const float* conv_w = (const float*)d_in[4];
    const float* conv_b = (const float*)d_in[5];
    const float* z_w    = (const float*)d_in[6];
    const float* i_w    = (const float*)d_in[7];
    const float* i_b    = (const float*)d_in[8];
    const float* f_w    = (const float*)d_in[9];
    const float* f_b    = (const float*)d_in[10];
    const float* o_w    = (const float*)d_in[11];
    const float* o_b    = (const float*)d_in[12];
    const float* gn_w   = (const float*)d_in[13];
    const float* gn_b   = (const float*)d_in[14];
    const float* out_w  = (const float*)d_in[15];

    float* out   = (float*)d_out;
    float* c_new = out + (size_t)BSZ * DM;
    float* n_new = c_new + (size_t)BSZ * NHD * HD;
    float* m_new = n_new + (size_t)BSZ * NHD * HD;

    cudaFuncSetAttribute(hmma_gemm_kernel<0>, cudaFuncAttributeMaxDynamicSharedMemorySize, SMEM_TOTAL);
    cudaFuncSetAttribute(hmma_gemm_kernel<1>, cudaFuncAttributeMaxDynamicSharedMemorySize, SMEM_TOTAL);

    // 1) prep: pack weights + convert inputs + reset mtile counters
    prep_kernel<<<6144 + BSZ, 256>>>(conv_w, z_w, out_w, inputs);

    // 2) GEMM1: [xconv | z] with fused last-CTA gates+cell+LN per mtile
    hmma_gemm_kernel<0><<<dim3(8, NMTILE), 288, SMEM_TOTAL>>>(
        conv_b, nullptr, inputs, i_w, i_b, f_w, f_b, o_w, o_b,
        m, m_new, c, n, gn_w, gn_b, c_new, n_new);

    // 3) GEMM2: out = h_norm @ out_w^T
    hmma_gemm_kernel<1><<<dim3(4, NMTILE), 288, SMEM_TOTAL>>>(
        nullptr, out, nullptr, nullptr, nullptr, nullptr, nullptr, nullptr,
        nullptr, nullptr, nullptr, nullptr, nullptr, nullptr, nullptr,
        nullptr, nullptr);
}

// round 16
// speedup vs baseline: 1.4806x; 1.4806x over previous
#include <cuda_runtime.h>
#include <cuda_bf16.h>
#include <math.h>
#include <stdint.h>

// ---------------- problem constants ----------------
#define BSZ 32768
#define DM  1024
#define NHD 8
#define HD  128
#define HIDM 1024
#define KSZ 4
#define EPSV 1e-6f
#define CAPV 15.0f

// split scale: s = 1/16
#define SPLIT_S    0.0625f
#define SPLIT_INV  16.0f
#define SPLIT_1MS  0.9375f

// ---------------- GEMM tiling ----------------
#define NCHUNK 32            // K_eff = 2048 = 32 chunks of 64 bf16 (16 main + 16 cor)
#define NS 4                 // pipeline stages
#define TM 128
#define TN 256
#define CHUNK_A 16384        // 128 rows x 128B (64 bf16)
#define CHUNK_B 32768        // 256 rows x 128B
#define STG (CHUNK_A + CHUNK_B)
#define SMEM_OFF 1024
#define SMEM_TOTAL (SMEM_OFF + NS * STG)

#define NMTILE (BSZ / TM)    // 256

// ---------------- device scratch (no allocs) ----------------
__device__ __nv_bfloat16 g_Ahi[(size_t)BSZ * DM];
__device__ __nv_bfloat16 g_Acor[(size_t)BSZ * DM];
__device__ __nv_bfloat16 g_Hhi[(size_t)BSZ * HIDM];
__device__ __nv_bfloat16 g_Hcor[(size_t)BSZ * HIDM];
__device__ __nv_bfloat16 g_W1[(size_t)2048 * 2048];   // [ntile8(256)][32][256x64 swz]
__device__ __nv_bfloat16 g_W2[(size_t)1024 * 2048];   // [ntile4(256)][32][256x64 swz]
__device__ float g_xconv[(size_t)BSZ * DM];
__device__ float g_z[(size_t)BSZ * HIDM];
__device__ float g_og[BSZ * NHD];

// ---------------- PTX helpers (all non-'a' features) ----------------
__device__ __forceinline__ uint32_t swz128(uint32_t off) { return off ^ ((off >> 3) & 0x70); }

__device__ __forceinline__ uint32_t s2u(const void* p) {
    uint32_t a;
    asm("{ .reg .u64 t; cvta.to.shared.u64 t, %1; cvt.u32.u64 %0, t; }" : "=r"(a) : "l"(p));
    return a;
}
__device__ __forceinline__ void mbar_init(uint32_t mbar, uint32_t cnt) {
    asm volatile("mbarrier.init.shared.b64 [%0], %1;" :: "r"(mbar), "r"(cnt) : "memory");
}
__device__ __forceinline__ void mbar_expect(uint32_t mbar, uint32_t bytes) {
    asm volatile("mbarrier.arrive.expect_tx.shared.b64 _, [%0], %1;" :: "r"(mbar), "r"(bytes) : "memory");
}
__device__ __forceinline__ void mbar_arrive(uint32_t mbar) {
    asm volatile("mbarrier.arrive.shared.b64 _, [%0];" :: "r"(mbar) : "memory");
}
__device__ __forceinline__ void mbar_wait(uint32_t mbar, uint32_t parity) {
    uint32_t done;
    asm volatile("{\n\t.reg .pred p;\n\t"
        "mbarrier.try_wait.parity.acquire.cta.shared::cta.b64 p, [%1], %2;\n\t"
        "selp.b32 %0, 1, 0, p;\n\t}"
        : "=r"(done) : "r"(mbar), "r"(parity) : "memory");
    while (!done) {
        asm volatile("{\n\t.reg .pred p;\n\t"
            "mbarrier.try_wait.parity.acquire.cta.shared::cta.b64 p, [%1], %2, 0x989680;\n\t"
            "selp.b32 %0, 1, 0, p;\n\t}"
            : "=r"(done) : "r"(mbar), "r"(parity) : "memory");
    }
}
__device__ __forceinline__ void bulk_g2s(uint32_t dst, const void* src, uint32_t bytes, uint32_t mbar) {
    asm volatile("cp.async.bulk.shared::cluster.global.mbarrier::complete_tx::bytes [%0], [%1], %2, [%3];"
        :: "r"(dst), "l"(src), "r"(bytes), "r"(mbar) : "memory");
}
__device__ __forceinline__ void ldmx4(uint32_t* r, uint32_t addr) {
    asm volatile("ldmatrix.sync.aligned.m8n8.x4.shared.b16 {%0,%1,%2,%3}, [%4];"
        : "=r"(r[0]), "=r"(r[1]), "=r"(r[2]), "=r"(r[3]) : "r"(addr));
}
__device__ __forceinline__ void mma16816(float* d, const uint32_t* a, uint32_t b0, uint32_t b1) {
    asm volatile("mma.sync.aligned.m16n8k16.row.col.f32.bf16.bf16.f32 "
        "{%0,%1,%2,%3}, {%4,%5,%6,%7}, {%8,%9}, {%0,%1,%2,%3};"
        : "+f"(d[0]), "+f"(d[1]), "+f"(d[2]), "+f"(d[3])
        : "r"(a[0]), "r"(a[1]), "r"(a[2]), "r"(a[3]), "r"(b0), "r"(b1));
}

__device__ __forceinline__ float softcap_f(float x) {
    return CAPV * tanhf(x * (1.0f / CAPV));
}

// ---------------- prep: weight pack + input convert + o-gate ---------------
// blocks [0, 6144): weight packing (W1=[conv_tap|z_w], W2=out_w),
//   segments per N-tile of 256 rows: [0:16)=W_hi, [16:32)=W_cor=bf16(W_hi+W_lo/s).
// blocks [6144, 6144+BSZ): one block per batch row: inputs -> blocked swizzled
//   bf16 hi/cor AND o-gate dot -> g_og (sigmoid(softcap(inp.o_w+o_b))).
__global__ __launch_bounds__(256) void prep_kernel(const float* __restrict__ conv_w,
                                                   const float* __restrict__ z_w,
                                                   const float* __restrict__ out_w,
                                                   const float* __restrict__ inp,
                                                   const float* __restrict__ o_w,
                                                   const float* __restrict__ o_b) {
    __shared__ float sred[8][NHD];
    if (blockIdx.x < 6144) {
        int idx = blockIdx.x * 256 + threadIdx.x;   // < 3072*512
        int n = idx >> 9;
        int k = (idx & 511) << 1;
        float v0, v1;
        if (n < 1024) {
            v0 = conv_w[((size_t)n * DM + k) * KSZ + (KSZ - 1)];
            v1 = conv_w[((size_t)n * DM + k + 1) * KSZ + (KSZ - 1)];
        } else if (n < 2048) {
            const float* p = &z_w[(size_t)(n - 1024) * DM + k];
            v0 = p[0]; v1 = p[1];
        } else {
            const float* p = &out_w[(size_t)(n - 2048) * DM + k];
            v0 = p[0]; v1 = p[1];
        }
        __nv_bfloat16 h0 = __float2bfloat16(v0), h1 = __float2bfloat16(v1);
        float h0f = __bfloat162float(h0), h1f = __bfloat162float(h1);
        __nv_bfloat162 hp; hp.x = h0; hp.y = h1;
        __nv_bfloat162 cp;
        cp.x = __float2bfloat16(h0f + (v0 - h0f) * SPLIT_INV);
        cp.y = __float2bfloat16(h1f + (v1 - h1f) * SPLIT_INV);

        char* base; int nl;
        if (n < 2048) { base = (char*)g_W1; nl = n; }
        else          { base = (char*)g_W2; nl = n - 2048; }
        int ntile = nl >> 8, nr = nl & 255;
        int kc = k >> 6;
        uint32_t inoff = swz128((uint32_t)nr * 128 + (uint32_t)(k & 63) * 2);
        size_t b0 = ((size_t)(ntile * NCHUNK + kc)) * CHUNK_B + inoff;
        size_t b1 = ((size_t)(ntile * NCHUNK + 16 + kc)) * CHUNK_B + inoff;
        *(__nv_bfloat162*)(base + b0) = hp;
        *(__nv_bfloat162*)(base + b1) = cp;
    } else {
        int b = blockIdx.x - 6144;                  // batch row
        int t = threadIdx.x;
        int k = t << 2;
        int wid = t >> 5, lane = t & 31;
        float4 v = *(const float4*)&inp[(size_t)b * DM + k];

        // bf16 hi/cor convert + blocked swizzled store
        __nv_bfloat16 h0 = __float2bfloat16(v.x), h1 = __float2bfloat16(v.y);
        __nv_bfloat16 h2 = __float2bfloat16(v.z), h3 = __float2bfloat16(v.w);
        float f0 = __bfloat162float(h0), f1 = __bfloat162float(h1);
        float f2 = __bfloat162float(h2), f3 = __bfloat162float(h3);
        __nv_bfloat162 hp0; hp0.x = h0; hp0.y = h1;
        __nv_bfloat162 hp1; hp1.x = h2; hp1.y = h3;
        __nv_bfloat162 cp0, cp1;
        cp0.x = __float2bfloat16((v.x - f0) + f0 * SPLIT_S);
        cp0.y = __float2bfloat16((v.y - f1) + f1 * SPLIT_S);
        cp1.x = __float2bfloat16((v.z - f2) + f2 * SPLIT_S);
        cp1.y = __float2bfloat16((v.w - f3) + f3 * SPLIT_S);
        uint2 hu, lu;
        hu.x = *(uint32_t*)&hp0; hu.y = *(uint32_t*)&hp1;
        lu.x = *(uint32_t*)&cp0; lu.y = *(uint32_t*)&cp1;
        int mtile = b >> 7, r = b & 127, kc = k >> 6;
        size_t off = ((size_t)(mtile * 16 + kc)) * CHUNK_A +
                     swz128((uint32_t)r * 128 + (uint32_t)(k & 63) * 2);
        *(uint2*)((char*)g_Ahi + off) = hu;
        *(uint2*)((char*)g_Acor + off) = lu;

        // o-gate dot: po[h] = partial of inp_row . o_w[h]
        float po[NHD];
#pragma unroll
        for (int h = 0; h < NHD; h++) {
            float4 w = *(const float4*)&o_w[h * DM + k];
            po[h] = v.x * w.x + v.y * w.y + v.z * w.z + v.w * w.w;
        }
#pragma unroll
        for (int offr = 16; offr > 0; offr >>= 1)
#pragma unroll
            for (int h = 0; h < NHD; h++)
                po[h] += __shfl_xor_sync(0xffffffffu, po[h], offr);
        if (lane == 0)
#pragma unroll
            for (int h = 0; h < NHD; h++) sred[wid][h] = po[h];
        __syncthreads();
        if (t < NHD) {
            float dz = 0.f;
#pragma unroll
            for (int w = 0; w < 8; w++) dz += sred[w][t];
            float ot = softcap_f(dz + o_b[t]);
            g_og[b * NHD + t] = 1.0f / (1.0f + expf(-ot));
        }
    }
}

// ---------------- HMMA GEMM, tile 128x256, K_eff=2048 (compensated 2-seg) --
// 9 warps: warp 8 = bulk-copy producer, warps 0-7 = 64x64 compute tiles (2x4).
// acc = P1 (chunks 0-15); acc *= (1-s); acc += P2 (chunks 16-31).
// MODE 0: W=g_W1 (N=2048): ntile<4 -> silu(+bias) -> g_xconv, else -> g_z.
// MODE 1: W=g_W2 (N=1024): plain store -> out.
template <int MODE>
__global__ __launch_bounds__(288, 1) void hmma_gemm_kernel(const float* __restrict__ bias,
                                                           float* __restrict__ outp) {
    extern __shared__ __align__(1024) char smem[];
    uint32_t sb = s2u(smem);
    const int tid = threadIdx.x, wid = tid >> 5, lane = tid & 31;
    const int mtile = blockIdx.y, ntile = blockIdx.x;

    if (tid == 0) {
        for (int s = 0; s < NS; s++) {
            mbar_init(sb + s * 8, 1);          // full (tx-based)
            mbar_init(sb + 64 + s * 8, 8);     // empty (8 consumer warps)
        }
        asm volatile("fence.proxy.async.shared::cta;" ::: "memory");
    }
    __syncthreads();

    if (wid == 8) {
        if (lane == 0) {
            const __nv_bfloat16* Ahi  = MODE ? g_Hhi  : g_Ahi;
            const __nv_bfloat16* Acor = MODE ? g_Hcor : g_Acor;
            const __nv_bfloat16* W    = MODE ? g_W2   : g_W1;
            for (int c = 0; c < NCHUNK; c++) {
                int s = c & (NS - 1);
                mbar_wait(sb + 64 + s * 8, 1u ^ ((c >> 2) & 1));
                uint32_t full = sb + s * 8;
                mbar_expect(full, STG);
                int seg = c >> 4, kk = c & 15;
                const char* ab = (const char*)(seg ? Acor : Ahi) +
                                 ((size_t)(mtile * 16 + kk)) * CHUNK_A;
                const char* bb = (const char*)W + ((size_t)(ntile * NCHUNK + c)) * CHUNK_B;
                uint32_t da = sb + SMEM_OFF + s * STG;
                bulk_g2s(da, ab, CHUNK_A, full);
                bulk_g2s(da + CHUNK_A, bb, CHUNK_B, full);
            }
        }
        return;
    }

    // consumers: warp (wm, wn) computes 64x64
    const int wm = wid >> 2, wn = wid & 3;
    const int m0 = wm * 64, n0 = wn * 64;
    const int li = lane & 7, lg = lane >> 3;

    float d[32][4];
#pragma unroll
    for (int i = 0; i < 32; i++)
#pragma unroll
        for (int j = 0; j < 4; j++) d[i][j] = 0.0f;

    uint32_t aoff[4], boff[4];
#pragma unroll
    for (int mt = 0; mt < 4; mt++)
        aoff[mt] = (uint32_t)(m0 + mt * 16 + 8 * (lg & 1) + li) * 128;
#pragma unroll
    for (int bt = 0; bt < 4; bt++)
        boff[bt] = (uint32_t)(n0 + bt * 16 + 8 * (lg >> 1) + li) * 128;
    const uint32_t acb = (uint32_t)(lg >> 1) * 16;
    const uint32_t bcb = (uint32_t)(lg & 1) * 16;
    const uint32_t sw  = (uint32_t)li * 16;

    for (int c = 0; c < NCHUNK; c++) {
        int s = c & (NS - 1);
        mbar_wait(sb + s * 8, (c >> 2) & 1);
        uint32_t ab = sb + SMEM_OFF + s * STG;
        uint32_t bb = ab + CHUNK_A;
#pragma unroll
        for (int ks = 0; ks < 4; ks++) {
            uint32_t k2 = (uint32_t)ks * 32;
            uint32_t a[4][4], bf[4][4];
#pragma unroll
            for (int mt = 0; mt < 4; mt++)
                ldmx4(a[mt], ab + aoff[mt] + ((k2 + acb) ^ sw));
#pragma unroll
            for (int bt = 0; bt < 4; bt++)
                ldmx4(bf[bt], bb + boff[bt] + ((k2 + bcb) ^ sw));
#pragma unroll
            for (int mt = 0; mt < 4; mt++)
#pragma unroll
                for (int nt = 0; nt < 8; nt++)
                    mma16816(d[mt * 8 + nt], a[mt],
                             bf[nt >> 1][(nt & 1) * 2], bf[nt >> 1][(nt & 1) * 2 + 1]);
        }
        if (lane == 0) mbar_arrive(sb + 64 + s * 8);
        if (c == 15) {
#pragma unroll
            for (int i = 0; i < 32; i++)
#pragma unroll
                for (int j = 0; j < 4; j++) d[i][j] *= SPLIT_1MS;
        }
    }

    // epilogue
    const int mrow = mtile * TM + m0 + (lane >> 2);
    const int gnb  = ntile * TN + n0 + (lane & 3) * 2;
#pragma unroll
    for (int mt = 0; mt < 4; mt++) {
#pragma unroll
        for (int nt = 0; nt < 8; nt++) {
            const float* dd = d[mt * 8 + nt];
            int gm = mrow + mt * 16;
            int gn = gnb + nt * 8;
            if (MODE == 0) {
                if (ntile < 4) {
                    float a0 = dd[0] + bias[gn], a1 = dd[1] + bias[gn + 1];
                    float a2 = dd[2] + bias[gn], a3 = dd[3] + bias[gn + 1];
                    float2 lo, hi;
                    lo.x = a0 / (1.0f + __expf(-a0)); lo.y = a1 / (1.0f + __expf(-a1));
                    hi.x = a2 / (1.0f + __expf(-a2)); hi.y = a3 / (1.0f + __expf(-a3));
                    *(float2*)&g_xconv[(size_t)gm * DM + gn] = lo;
                    *(float2*)&g_xconv[(size_t)(gm + 8) * DM + gn] = hi;
                } else {
                    float2 lo = {dd[0], dd[1]}, hi = {dd[2], dd[3]};
                    int zc = gn - DM;
                    *(float2*)&g_z[(size_t)gm * HIDM + zc] = lo;
                    *(float2*)&g_z[(size_t)(gm + 8) * HIDM + zc] = hi;
                }
            } else {
                float2 lo = {dd[0], dd[1]}, hi = {dd[2], dd[3]};
                *(float2*)&outp[(size_t)gm * DM + gn] = lo;
                *(float2*)&outp[(size_t)(gm + 8) * DM + gn] = hi;
            }
        }
    }
}

// ---------------- fused gates (i/f) + elementwise + per-head LN ------------
// One block (256 thr) per batch row; warp h handles head h. o-gate comes
// precomputed from prep (g_og). All phase-2 operands prefetched before the
// dot phase so their DRAM latency hides behind compute.
__global__ __launch_bounds__(256) void gact_kernel(
    const float* __restrict__ i_w, const float* __restrict__ i_b,
    const float* __restrict__ f_w, const float* __restrict__ f_b,
    const float* __restrict__ m_in, float* __restrict__ m_out,
    const float* __restrict__ c, const float* __restrict__ n,
    const float* __restrict__ gn_w, const float* __restrict__ gn_b,
    float* __restrict__ c_new, float* __restrict__ n_new) {
    __shared__ float s_xc[DM];

    const int b = blockIdx.x;
    const int t = threadIdx.x;
    const int h = t >> 5;
    const int lane = t & 31;

    // ---- prefetch phase-2 operands (independent of gates) ----
    const int e = lane * 4;
    const int col = h * HD + e;
    const size_t base = (size_t)(b * NHD + h) * HD + e;
    float4 c4 = *(const float4*)&c[base];
    float4 n4 = *(const float4*)&n[base];
    float4 z4 = *(const float4*)&g_z[(size_t)b * HIDM + col];
    float4 gw = *(const float4*)&gn_w[col];
    float4 gb = *(const float4*)&gn_b[col];
    const float og = g_og[b * NHD + h];
    const float mv = m_in[b * NHD + h];

    // stage xconv row (float4; 256 thr x 4 = 1024)
    *(float4*)&s_xc[t * 4] = *(const float4*)&g_xconv[(size_t)b * DM + t * 4];
    __syncthreads();

    // ---- i/f gate dots (warp h -> head h), float4, butterfly-reduced ----
    const float* iw = &i_w[h * DM];
    const float* fw = &f_w[h * DM];
    float di = 0.f, df = 0.f;
#pragma unroll
    for (int it = 0; it < 8; it++) {
        int k = it * 128 + lane * 4;
        float4 x = *(const float4*)&s_xc[k];
        float4 wi = *(const float4*)&iw[k];
        float4 wf = *(const float4*)&fw[k];
        di += x.x * wi.x + x.y * wi.y + x.z * wi.z + x.w * wi.w;
        df += x.x * wf.x + x.y * wf.y + x.z * wf.z + x.w * wf.w;
    }
#pragma unroll
    for (int off = 16; off > 0; off >>= 1) {
        di += __shfl_xor_sync(0xffffffffu, di, off);
        df += __shfl_xor_sync(0xffffffffu, df, off);
    }
    float itv = softcap_f(di + i_b[h]);
    float ftv = softcap_f(df + f_b[h]);
    float flog = -log1pf(expf(-ftv));
    float mn   = fmaxf(flog + mv, itv);
    float ig = expf(itv - mn);
    float fg = expf(flog + mv - mn);
    if (lane == 0) m_out[b * NHD + h] = mn;

    // ---- cell update + LN (warp h -> head h, 4 elems/lane) ----
    float cv[4], nv[4], hv[4];
    cv[0] = fg * c4.x + ig * z4.x; cv[1] = fg * c4.y + ig * z4.y;
    cv[2] = fg * c4.z + ig * z4.z; cv[3] = fg * c4.w + ig * z4.w;
    nv[0] = fg * n4.x + ig; nv[1] = fg * n4.y + ig;
    nv[2] = fg * n4.z + ig; nv[3] = fg * n4.w + ig;
#pragma unroll
    for (int j = 0; j < 4; j++) hv[j] = og * cv[j] / (nv[j] + EPSV);

    *(float4*)&c_new[base] = *(float4*)cv;
    *(float4*)&n_new[base] = *(float4*)nv;

    float s = hv[0] + hv[1] + hv[2] + hv[3];
    float s2 = hv[0] * hv[0] + hv[1] * hv[1] + hv[2] * hv[2] + hv[3] * hv[3];
#pragma unroll
    for (int off = 16; off > 0; off >>= 1) {
        s  += __shfl_xor_sync(0xffffffffu, s, off);
        s2 += __shfl_xor_sync(0xffffffffu, s2, off);
    }
    float mu  = s * (1.0f / HD);
    float var = s2 * (1.0f / HD) - mu * mu;
    float rs  = rsqrtf(var + EPSV);

    float hn[4];
    hn[0] = (hv[0] - mu) * rs * gw.x + gb.x;
    hn[1] = (hv[1] - mu) * rs * gw.y + gb.y;
    hn[2] = (hv[2] - mu) * rs * gw.z + gb.z;
    hn[3] = (hv[3] - mu) * rs * gw.w + gb.w;

    __nv_bfloat162 hp0, hp1, cp0, cp1;
    hp0.x = __float2bfloat16(hn[0]); hp0.y = __float2bfloat16(hn[1]);
    hp1.x = __float2bfloat16(hn[2]); hp1.y = __float2bfloat16(hn[3]);
    float f0 = __bfloat162float(hp0.x), f1 = __bfloat162float(hp0.y);
    float f2 = __bfloat162float(hp1.x), f3 = __bfloat162float(hp1.y);
    cp0.x = __float2bfloat16((hn[0] - f0) + f0 * SPLIT_S);
    cp0.y = __float2bfloat16((hn[1] - f1) + f1 * SPLIT_S);
    cp1.x = __float2bfloat16((hn[2] - f2) + f2 * SPLIT_S);
    cp1.y = __float2bfloat16((hn[3] - f3) + f3 * SPLIT_S);
    uint2 hu, lu;
    hu.x = *(uint32_t*)&hp0; hu.y = *(uint32_t*)&hp1;
    lu.x = *(uint32_t*)&cp0; lu.y = *(uint32_t*)&cp1;

    int mtile = b >> 7, r = b & 127, kc = col >> 6;
    size_t off2 = ((size_t)(mtile * 16 + kc)) * CHUNK_A +
                  swz128((uint32_t)r * 128 + (uint32_t)(col & 63) * 2);
    *(uint2*)((char*)g_Hhi + off2) = hu;
    *(uint2*)((char*)g_Hcor + off2) = lu;
}

// ---------------- launch ------------------------------------------
extern "C" void kernel_launch(void* const* d_in, const int* in_sizes, int n_in,
                              void* d_out, int out_size) {
    const float* inputs = (const float*)d_in[0];
    const float* c      = (const float*)d_in[1];
    const float* n      = (const float*)d_in[2];
    const float* m      = (const float*)d_in[3];
    const float* conv_w = (const float*)d_in[4];
    const float* conv_b = (const float*)d_in[5];
    const float* z_w    = (const float*)d_in[6];
    const float* i_w    = (const float*)d_in[7];
    const float* i_b    = (const float*)d_in[8];
    const float* f_w    = (const float*)d_in[9];
    const float* f_b    = (const float*)d_in[10];
    const float* o_w    = (const float*)d_in[11];
    const float* o_b    = (const float*)d_in[12];
    const float* gn_w   = (const float*)d_in[13];
    const float* gn_b   = (const float*)d_in[14];
    const float* out_w  = (const float*)d_in[15];

    float* out   = (float*)d_out;
    float* c_new = out + (size_t)BSZ * DM;
    float* n_new = c_new + (size_t)BSZ * NHD * HD;
    float* m_new = n_new + (size_t)BSZ * NHD * HD;

    cudaFuncSetAttribute(hmma_gemm_kernel<0>, cudaFuncAttributeMaxDynamicSharedMemorySize, SMEM_TOTAL);
    cudaFuncSetAttribute(hmma_gemm_kernel<1>, cudaFuncAttributeMaxDynamicSharedMemorySize, SMEM_TOTAL);

    // 1) prep: pack weights + convert inputs + o-gate
    prep_kernel<<<6144 + BSZ, 256>>>(conv_w, z_w, out_w, inputs, o_w, o_b);

    // 2) GEMM1: [xconv | z]
    hmma_gemm_kernel<0><<<dim3(8, NMTILE), 288, SMEM_TOTAL>>>(conv_b, nullptr);

    // 3) gates (i/f) + cell update + LN (emits h_norm bf16 hi/cor blocked)
    gact_kernel<<<BSZ, 256>>>(i_w, i_b, f_w, f_b, m, m_new,
                              c, n, gn_w, gn_b, c_new, n_new);

    // 4) GEMM2: out = h_norm @ out_w^T
    hmma_gemm_kernel<1><<<dim3(4, NMTILE), 288, SMEM_TOTAL>>>(nullptr, out);
}